// round 1
// baseline (speedup 1.0000x reference)
#include <cuda_runtime.h>
#include <math.h>

#define NB   4
#define HH_  128
#define WW_  128
#define CC_  128
#define GG_  8
#define GC_  16
#define KP   9
#define NPIX (NB * HH_ * WW_)   // 65536
#define EPSL 1e-5f

// -------------------- scratch (device globals; no allocation) --------------------
__device__ float g_x1n[(size_t)NPIX * CC_];
__device__ float g_xp [(size_t)NPIX * CC_];
__device__ float g_x1 [(size_t)NPIX * CC_];
__device__ float g_off[(size_t)NPIX * GG_ * KP * 2];
__device__ float g_ml [(size_t)NPIX * GG_ * KP];
__device__ float g_y  [(size_t)NPIX * CC_];
__device__ float g_x2 [(size_t)NPIX * CC_];
__device__ float g_h  [(size_t)NPIX * CC_];
__device__ float g_hh [(size_t)NPIX * 4 * CC_];

__device__ __forceinline__ float gelu_f(float x) {
    return 0.5f * x * (1.0f + erff(x * 0.7071067811865476f));
}

// -------------------- LayerNorm: one warp per pixel (C=128, float4/lane) --------------------
__global__ __launch_bounds__(256) void ln_kernel(const float* __restrict__ x,
                                                 const float* __restrict__ gw,
                                                 const float* __restrict__ bw,
                                                 float* __restrict__ out) {
    int pix  = blockIdx.x * 8 + (threadIdx.x >> 5);
    int lane = threadIdx.x & 31;
    const float4 v = ((const float4*)(x + (size_t)pix * CC_))[lane];
    float s = v.x + v.y + v.z + v.w;
    #pragma unroll
    for (int o = 16; o > 0; o >>= 1) s += __shfl_xor_sync(0xffffffffu, s, o);
    float mean = s * (1.0f / CC_);
    float dx = v.x - mean, dy = v.y - mean, dz = v.z - mean, dw = v.w - mean;
    float q = dx * dx + dy * dy + dz * dz + dw * dw;
    #pragma unroll
    for (int o = 16; o > 0; o >>= 1) q += __shfl_xor_sync(0xffffffffu, q, o);
    float r = rsqrtf(q * (1.0f / CC_) + EPSL);
    const float4 gg = ((const float4*)gw)[lane];
    const float4 bb = ((const float4*)bw)[lane];
    float4 o4;
    o4.x = dx * r * gg.x + bb.x;
    o4.y = dy * r * gg.y + bb.y;
    o4.z = dz * r * gg.z + bb.z;
    o4.w = dw * r * gg.w + bb.w;
    ((float4*)(out + (size_t)pix * CC_))[lane] = o4;
}

// -------------------- depthwise 3x3 conv + bias + LN + GELU: one warp per pixel --------------------
__global__ __launch_bounds__(256) void dw_ln_gelu_kernel(const float* __restrict__ x,
                                                         const float* __restrict__ kw,
                                                         const float* __restrict__ kb,
                                                         const float* __restrict__ gw,
                                                         const float* __restrict__ bw,
                                                         float* __restrict__ out) {
    int pix  = blockIdx.x * 8 + (threadIdx.x >> 5);
    int lane = threadIdx.x & 31;
    int n = pix >> 14;
    int hw = pix & 16383;
    int h = hw >> 7;
    int w = hw & 127;
    float4 acc = ((const float4*)kb)[lane];
    #pragma unroll
    for (int ky = 0; ky < 3; ky++) {
        int hh = h + ky - 1;
        if ((unsigned)hh >= (unsigned)HH_) continue;
        #pragma unroll
        for (int kx = 0; kx < 3; kx++) {
            int ww = w + kx - 1;
            if ((unsigned)ww >= (unsigned)WW_) continue;
            const float4 xv = ((const float4*)(x + (size_t)((n * HH_ + hh) * WW_ + ww) * CC_))[lane];
            const float4 kv = ((const float4*)(kw + (size_t)(ky * 3 + kx) * CC_))[lane];
            acc.x += xv.x * kv.x;
            acc.y += xv.y * kv.y;
            acc.z += xv.z * kv.z;
            acc.w += xv.w * kv.w;
        }
    }
    // LN over C=128 across the warp
    float s = acc.x + acc.y + acc.z + acc.w;
    #pragma unroll
    for (int o = 16; o > 0; o >>= 1) s += __shfl_xor_sync(0xffffffffu, s, o);
    float mean = s * (1.0f / CC_);
    float dx = acc.x - mean, dy = acc.y - mean, dz = acc.z - mean, dw = acc.w - mean;
    float q = dx * dx + dy * dy + dz * dz + dw * dw;
    #pragma unroll
    for (int o = 16; o > 0; o >>= 1) q += __shfl_xor_sync(0xffffffffu, q, o);
    float r = rsqrtf(q * (1.0f / CC_) + EPSL);
    const float4 gg = ((const float4*)gw)[lane];
    const float4 bb = ((const float4*)bw)[lane];
    float4 o4;
    o4.x = gelu_f(dx * r * gg.x + bb.x);
    o4.y = gelu_f(dy * r * gg.y + bb.y);
    o4.z = gelu_f(dz * r * gg.z + bb.z);
    o4.w = gelu_f(dw * r * gg.w + bb.w);
    ((float4*)(out + (size_t)pix * CC_))[lane] = o4;
}

// -------------------- generic SGEMM 64x64x16, bias + optional GELU / residual --------------------
template <bool DOGELU, bool DORES>
__global__ __launch_bounds__(256) void sgemm_kernel(const float* __restrict__ A,
                                                    const float* __restrict__ B,
                                                    const float* __restrict__ bias,
                                                    const float* __restrict__ res,
                                                    float* __restrict__ Cmat,
                                                    int M, int Kd, int Nc) {
    const int BM = 64, BN = 64, BK = 16;
    __shared__ float As[BK][BM];
    __shared__ float Bs[BK][BN];
    int tid = threadIdx.x;
    int bm = blockIdx.y * BM;
    int bn = blockIdx.x * BN;
    int tx = tid & 15, ty = tid >> 4;
    float acc[4][4] = {};
    for (int k0 = 0; k0 < Kd; k0 += BK) {
        #pragma unroll
        for (int i = tid; i < BM * BK; i += 256) {
            int r = i >> 4, cc = i & 15;
            As[cc][r] = A[(size_t)(bm + r) * Kd + (k0 + cc)];
        }
        #pragma unroll
        for (int i = tid; i < BK * BN; i += 256) {
            int r = i >> 6, cc = i & 63;
            int col = bn + cc;
            Bs[r][cc] = (col < Nc) ? B[(size_t)(k0 + r) * Nc + col] : 0.0f;
        }
        __syncthreads();
        #pragma unroll
        for (int kk = 0; kk < BK; kk++) {
            float a[4], b[4];
            #pragma unroll
            for (int i = 0; i < 4; i++) a[i] = As[kk][ty * 4 + i];
            #pragma unroll
            for (int j = 0; j < 4; j++) b[j] = Bs[kk][tx * 4 + j];
            #pragma unroll
            for (int i = 0; i < 4; i++)
                #pragma unroll
                for (int j = 0; j < 4; j++)
                    acc[i][j] += a[i] * b[j];
        }
        __syncthreads();
    }
    #pragma unroll
    for (int i = 0; i < 4; i++) {
        int row = bm + ty * 4 + i;
        #pragma unroll
        for (int j = 0; j < 4; j++) {
            int col = bn + tx * 4 + j;
            if (col < Nc) {
                float v = acc[i][j] + bias[col];
                if (DOGELU) v = gelu_f(v);
                if (DORES) v += res[(size_t)row * Nc + col];
                Cmat[(size_t)row * Nc + col] = v;
            }
        }
    }
}

// -------------------- deformable sampling core: 1 block = 1 pixel, thread = channel --------------------
__device__ __forceinline__ float dcn_sample(const float* __restrict__ xp, int n, int yi, int xi, int c) {
    // padded coordinates: valid data lives at [1..H] x [1..W]; ring & OOB are zero
    if (yi < 1 || yi > HH_ || xi < 1 || xi > WW_) return 0.0f;
    return xp[(size_t)((n * HH_ + (yi - 1)) * WW_ + (xi - 1)) * CC_ + c];
}

__global__ __launch_bounds__(128) void dcn_kernel(const float* __restrict__ xp,
                                                  const float* __restrict__ off,
                                                  const float* __restrict__ ml,
                                                  float* __restrict__ y) {
    int pix = blockIdx.x;
    int c = threadIdx.x;
    int g = c >> 4;
    int n = pix >> 14;
    int hw = pix & 16383;
    int h = hw >> 7;
    int w = hw & 127;
    const float* o = off + (size_t)pix * (GG_ * KP * 2) + g * (KP * 2);
    const float* m = ml + (size_t)pix * (GG_ * KP) + g * KP;
    float lg[KP];
    float mx = -1e30f;
    #pragma unroll
    for (int k = 0; k < KP; k++) { lg[k] = m[k]; mx = fmaxf(mx, lg[k]); }
    float ssum = 0.0f;
    #pragma unroll
    for (int k = 0; k < KP; k++) { lg[k] = expf(lg[k] - mx); ssum += lg[k]; }
    float inv = 1.0f / ssum;
    float acc = 0.0f;
    #pragma unroll
    for (int k = 0; k < KP; k++) {
        // px = w + 1 + (k/3 - 1) + off_x ; py = h + 1 + (k%3 - 1) + off_y  (padded coords)
        float px = (float)(w + (k / 3)) + o[2 * k];
        float py = (float)(h + (k % 3)) + o[2 * k + 1];
        float fx = floorf(px), fy = floorf(py);
        float tx = px - fx, ty = py - fy;
        int x0 = (int)fx, y0 = (int)fy;
        float v00 = dcn_sample(xp, n, y0,     x0,     c);
        float v01 = dcn_sample(xp, n, y0,     x0 + 1, c);
        float v10 = dcn_sample(xp, n, y0 + 1, x0,     c);
        float v11 = dcn_sample(xp, n, y0 + 1, x0 + 1, c);
        float bi = (1.0f - ty) * ((1.0f - tx) * v00 + tx * v01)
                 + ty * ((1.0f - tx) * v10 + tx * v11);
        acc += lg[k] * inv * bi;
    }
    y[(size_t)pix * CC_ + c] = acc;
}

// -------------------- launch --------------------
extern "C" void kernel_launch(void* const* d_in, const int* in_sizes, int n_in,
                              void* d_out, int out_size) {
    const float* x      = (const float*)d_in[0];
    const float* ln1_g  = (const float*)d_in[1];
    const float* ln1_b  = (const float*)d_in[2];
    const float* in_w   = (const float*)d_in[3];
    const float* in_b   = (const float*)d_in[4];
    const float* dw_k   = (const float*)d_in[5];
    const float* dw_b   = (const float*)d_in[6];
    const float* dwln_g = (const float*)d_in[7];
    const float* dwln_b = (const float*)d_in[8];
    const float* off_w  = (const float*)d_in[9];
    const float* off_b  = (const float*)d_in[10];
    const float* mask_w = (const float*)d_in[11];
    const float* mask_b = (const float*)d_in[12];
    const float* out_w  = (const float*)d_in[13];
    const float* out_b  = (const float*)d_in[14];
    const float* ln2_g  = (const float*)d_in[15];
    const float* ln2_b  = (const float*)d_in[16];
    const float* fc1_w  = (const float*)d_in[17];
    const float* fc1_b  = (const float*)d_in[18];
    const float* fc2_w  = (const float*)d_in[19];
    const float* fc2_b  = (const float*)d_in[20];
    float* out = (float*)d_out;

    float *x1n, *xp, *x1, *off, *ml, *y, *x2, *h, *hh;
    cudaGetSymbolAddress((void**)&x1n, g_x1n);
    cudaGetSymbolAddress((void**)&xp,  g_xp);
    cudaGetSymbolAddress((void**)&x1,  g_x1);
    cudaGetSymbolAddress((void**)&off, g_off);
    cudaGetSymbolAddress((void**)&ml,  g_ml);
    cudaGetSymbolAddress((void**)&y,   g_y);
    cudaGetSymbolAddress((void**)&x2,  g_x2);
    cudaGetSymbolAddress((void**)&h,   g_h);
    cudaGetSymbolAddress((void**)&hh,  g_hh);

    const int M = NPIX;
    dim3 blk256(256);

    // 1. LN1
    ln_kernel<<<NPIX / 8, blk256>>>(x, ln1_g, ln1_b, x1n);
    // 2. input_proj: xp = x1n @ in_w + in_b
    sgemm_kernel<false, false><<<dim3(2, M / 64), blk256>>>(x1n, in_w, in_b, nullptr, xp, M, 128, 128);
    // 3. depthwise conv + LN + GELU -> x1
    dw_ln_gelu_kernel<<<NPIX / 8, blk256>>>(x1n, dw_k, dw_b, dwln_g, dwln_b, x1);
    // 4. offset = x1 @ off_w + off_b   (N=144)
    sgemm_kernel<false, false><<<dim3(3, M / 64), blk256>>>(x1, off_w, off_b, nullptr, off, M, 128, 144);
    // 5. mask logits = x1 @ mask_w + mask_b   (N=72)
    sgemm_kernel<false, false><<<dim3(2, M / 64), blk256>>>(x1, mask_w, mask_b, nullptr, ml, M, 128, 72);
    // 6. deformable sampling (softmax fused)
    dcn_kernel<<<NPIX, dim3(128)>>>(xp, off, ml, y);
    // 7. x2 = y @ out_w + out_b + x
    sgemm_kernel<false, true><<<dim3(2, M / 64), blk256>>>(y, out_w, out_b, x, x2, M, 128, 128);
    // 8. LN2
    ln_kernel<<<NPIX / 8, blk256>>>(x2, ln2_g, ln2_b, h);
    // 9. hh = gelu(h @ fc1_w + fc1_b)   (N=512)
    sgemm_kernel<true, false><<<dim3(8, M / 64), blk256>>>(h, fc1_w, fc1_b, nullptr, hh, M, 128, 512);
    // 10. out = hh @ fc2_w + fc2_b + x2
    sgemm_kernel<false, true><<<dim3(2, M / 64), blk256>>>(hh, fc2_w, fc2_b, x2, out, M, 512, 128);
}

// round 2
// speedup vs baseline: 2.2888x; 2.2888x over previous
#include <cuda_runtime.h>
#include <math.h>
#include <stdint.h>

#define NB   4
#define HH_  128
#define WW_  128
#define CC_  128
#define GG_  8
#define GC_  16
#define KP   9
#define NPIX (NB * HH_ * WW_)   // 65536
#define EPSL 1e-5f

// -------------------- scratch (device globals; no allocation) --------------------
__device__ float g_x1n[(size_t)NPIX * CC_];
__device__ float g_xp [(size_t)NPIX * CC_];
__device__ float g_x1 [(size_t)NPIX * CC_];
__device__ float g_off[(size_t)NPIX * GG_ * KP * 2];
__device__ float g_ml [(size_t)NPIX * GG_ * KP];
__device__ float g_y  [(size_t)NPIX * CC_];
__device__ float g_x2 [(size_t)NPIX * CC_];
__device__ float g_h  [(size_t)NPIX * CC_];
__device__ float g_hh [(size_t)NPIX * 4 * CC_];

__device__ __forceinline__ float gelu_f(float x) {
    return 0.5f * x * (1.0f + erff(x * 0.7071067811865476f));
}

__device__ __forceinline__ float to_tf32(float x) {
    uint32_t u;
    asm("cvt.rna.tf32.f32 %0, %1;" : "=r"(u) : "f"(x));
    return __uint_as_float(u);
}

__device__ __forceinline__ void mma_tf32(float c[4],
                                         uint32_t a0, uint32_t a1, uint32_t a2, uint32_t a3,
                                         uint32_t b0, uint32_t b1) {
    asm volatile("mma.sync.aligned.m16n8k8.row.col.f32.tf32.tf32.f32 "
                 "{%0,%1,%2,%3}, {%4,%5,%6,%7}, {%8,%9}, {%0,%1,%2,%3};\n"
                 : "+f"(c[0]), "+f"(c[1]), "+f"(c[2]), "+f"(c[3])
                 : "r"(a0), "r"(a1), "r"(a2), "r"(a3), "r"(b0), "r"(b1));
}

// -------------------- LayerNorm: one warp per pixel (C=128, float4/lane) --------------------
__global__ __launch_bounds__(256) void ln_kernel(const float* __restrict__ x,
                                                 const float* __restrict__ gw,
                                                 const float* __restrict__ bw,
                                                 float* __restrict__ out) {
    int pix  = blockIdx.x * 8 + (threadIdx.x >> 5);
    int lane = threadIdx.x & 31;
    const float4 v = ((const float4*)(x + (size_t)pix * CC_))[lane];
    float s = v.x + v.y + v.z + v.w;
    #pragma unroll
    for (int o = 16; o > 0; o >>= 1) s += __shfl_xor_sync(0xffffffffu, s, o);
    float mean = s * (1.0f / CC_);
    float dx = v.x - mean, dy = v.y - mean, dz = v.z - mean, dw = v.w - mean;
    float q = dx * dx + dy * dy + dz * dz + dw * dw;
    #pragma unroll
    for (int o = 16; o > 0; o >>= 1) q += __shfl_xor_sync(0xffffffffu, q, o);
    float r = rsqrtf(q * (1.0f / CC_) + EPSL);
    const float4 gg = ((const float4*)gw)[lane];
    const float4 bb = ((const float4*)bw)[lane];
    float4 o4;
    o4.x = dx * r * gg.x + bb.x;
    o4.y = dy * r * gg.y + bb.y;
    o4.z = dz * r * gg.z + bb.z;
    o4.w = dw * r * gg.w + bb.w;
    ((float4*)(out + (size_t)pix * CC_))[lane] = o4;
}

// -------------------- depthwise 3x3 conv + bias + LN + GELU: one warp per pixel --------------------
__global__ __launch_bounds__(256) void dw_ln_gelu_kernel(const float* __restrict__ x,
                                                         const float* __restrict__ kw,
                                                         const float* __restrict__ kb,
                                                         const float* __restrict__ gw,
                                                         const float* __restrict__ bw,
                                                         float* __restrict__ out) {
    int pix  = blockIdx.x * 8 + (threadIdx.x >> 5);
    int lane = threadIdx.x & 31;
    int n = pix >> 14;
    int hw = pix & 16383;
    int h = hw >> 7;
    int w = hw & 127;
    float4 acc = ((const float4*)kb)[lane];
    #pragma unroll
    for (int ky = 0; ky < 3; ky++) {
        int hh = h + ky - 1;
        if ((unsigned)hh >= (unsigned)HH_) continue;
        #pragma unroll
        for (int kx = 0; kx < 3; kx++) {
            int ww = w + kx - 1;
            if ((unsigned)ww >= (unsigned)WW_) continue;
            const float4 xv = ((const float4*)(x + (size_t)((n * HH_ + hh) * WW_ + ww) * CC_))[lane];
            const float4 kv = ((const float4*)(kw + (size_t)(ky * 3 + kx) * CC_))[lane];
            acc.x += xv.x * kv.x;
            acc.y += xv.y * kv.y;
            acc.z += xv.z * kv.z;
            acc.w += xv.w * kv.w;
        }
    }
    float s = acc.x + acc.y + acc.z + acc.w;
    #pragma unroll
    for (int o = 16; o > 0; o >>= 1) s += __shfl_xor_sync(0xffffffffu, s, o);
    float mean = s * (1.0f / CC_);
    float dx = acc.x - mean, dy = acc.y - mean, dz = acc.z - mean, dw = acc.w - mean;
    float q = dx * dx + dy * dy + dz * dz + dw * dw;
    #pragma unroll
    for (int o = 16; o > 0; o >>= 1) q += __shfl_xor_sync(0xffffffffu, q, o);
    float r = rsqrtf(q * (1.0f / CC_) + EPSL);
    const float4 gg = ((const float4*)gw)[lane];
    const float4 bb = ((const float4*)bw)[lane];
    float4 o4;
    o4.x = gelu_f(dx * r * gg.x + bb.x);
    o4.y = gelu_f(dy * r * gg.y + bb.y);
    o4.z = gelu_f(dz * r * gg.z + bb.z);
    o4.w = gelu_f(dw * r * gg.w + bb.w);
    ((float4*)(out + (size_t)pix * CC_))[lane] = o4;
}

// -------------------- TF32 tensor-core GEMM: 128x128x16 block, 8 warps, 32x64 warp tile --------------------
// A[M,K] row-major, B[K,N] row-major, C[M,N]. Epilogue: +bias, optional GELU, optional residual.
template <bool DOGELU, bool DORES>
__global__ __launch_bounds__(256) void tgemm_kernel(const float* __restrict__ A,
                                                    const float* __restrict__ B,
                                                    const float* __restrict__ bias,
                                                    const float* __restrict__ res,
                                                    float* __restrict__ Cmat,
                                                    int M, int Kd, int Nc) {
    const int BM = 128, BN = 128, BK = 16;
    const int LDA = BM + 4;   // 132, conflict-free fragment loads
    const int LDB = BN + 4;
    __shared__ float As[2][BK][LDA];   // [k][m]
    __shared__ float Bs[2][BK][LDB];   // [k][n]

    int tid = threadIdx.x;
    int warp = tid >> 5;
    int lane = tid & 31;
    int lr = lane >> 2;       // 0..7
    int lk = lane & 3;        // 0..3
    int bm = blockIdx.y * BM;
    int bn = blockIdx.x * BN;
    int wm = (warp & 3) * 32;
    int wn = (warp >> 2) * 64;

    float c[2][8][4];
    #pragma unroll
    for (int mi = 0; mi < 2; mi++)
        #pragma unroll
        for (int ni = 0; ni < 8; ni++)
            #pragma unroll
            for (int q = 0; q < 4; q++) c[mi][ni][q] = 0.0f;

    // tile-load index precompute (each thread handles i = tid and tid+256)
    const int ar0 = tid >> 2,        akq0 = (tid & 3) * 4;          // A: row, k-quad
    const int ar1 = (tid + 256) >> 2, akq1 = ((tid + 256) & 3) * 4;
    const int bk0 = tid >> 5,        bc0 = (tid & 31) * 4;          // B: k-row, col
    const int bk1 = (tid + 256) >> 5, bc1 = ((tid + 256) & 31) * 4;

    auto load_tile = [&](int k0, int buf) {
        // A tile: 128 rows x 16 k
        {
            float4 v = *(const float4*)(A + (size_t)(bm + ar0) * Kd + k0 + akq0);
            As[buf][akq0 + 0][ar0] = to_tf32(v.x);
            As[buf][akq0 + 1][ar0] = to_tf32(v.y);
            As[buf][akq0 + 2][ar0] = to_tf32(v.z);
            As[buf][akq0 + 3][ar0] = to_tf32(v.w);
            v = *(const float4*)(A + (size_t)(bm + ar1) * Kd + k0 + akq1);
            As[buf][akq1 + 0][ar1] = to_tf32(v.x);
            As[buf][akq1 + 1][ar1] = to_tf32(v.y);
            As[buf][akq1 + 2][ar1] = to_tf32(v.z);
            As[buf][akq1 + 3][ar1] = to_tf32(v.w);
        }
        // B tile: 16 k x 128 n (guard columns)
        {
            float4 v = make_float4(0.f, 0.f, 0.f, 0.f);
            if (bn + bc0 < Nc) v = *(const float4*)(B + (size_t)(k0 + bk0) * Nc + bn + bc0);
            float4 t = make_float4(to_tf32(v.x), to_tf32(v.y), to_tf32(v.z), to_tf32(v.w));
            *(float4*)&Bs[buf][bk0][bc0] = t;
            v = make_float4(0.f, 0.f, 0.f, 0.f);
            if (bn + bc1 < Nc) v = *(const float4*)(B + (size_t)(k0 + bk1) * Nc + bn + bc1);
            t = make_float4(to_tf32(v.x), to_tf32(v.y), to_tf32(v.z), to_tf32(v.w));
            *(float4*)&Bs[buf][bk1][bc1] = t;
        }
    };

    load_tile(0, 0);
    __syncthreads();

    int nkb = Kd / BK;
    int buf = 0;
    for (int kb = 0; kb < nkb; kb++) {
        // prefetch next tile into registers
        float4 pa0, pa1, pb0, pb1;
        bool havenext = (kb + 1 < nkb);
        if (havenext) {
            int k0 = (kb + 1) * BK;
            pa0 = *(const float4*)(A + (size_t)(bm + ar0) * Kd + k0 + akq0);
            pa1 = *(const float4*)(A + (size_t)(bm + ar1) * Kd + k0 + akq1);
            pb0 = make_float4(0.f, 0.f, 0.f, 0.f);
            if (bn + bc0 < Nc) pb0 = *(const float4*)(B + (size_t)(k0 + bk0) * Nc + bn + bc0);
            pb1 = make_float4(0.f, 0.f, 0.f, 0.f);
            if (bn + bc1 < Nc) pb1 = *(const float4*)(B + (size_t)(k0 + bk1) * Nc + bn + bc1);
        }

        // compute on current buffer
        #pragma unroll
        for (int ks = 0; ks < BK; ks += 8) {
            uint32_t af[2][4];
            #pragma unroll
            for (int mi = 0; mi < 2; mi++) {
                int m0 = wm + mi * 16 + lr;
                af[mi][0] = __float_as_uint(As[buf][ks + lk][m0]);
                af[mi][1] = __float_as_uint(As[buf][ks + lk][m0 + 8]);
                af[mi][2] = __float_as_uint(As[buf][ks + lk + 4][m0]);
                af[mi][3] = __float_as_uint(As[buf][ks + lk + 4][m0 + 8]);
            }
            uint32_t bf[8][2];
            #pragma unroll
            for (int ni = 0; ni < 8; ni++) {
                int n0 = wn + ni * 8 + lr;
                bf[ni][0] = __float_as_uint(Bs[buf][ks + lk][n0]);
                bf[ni][1] = __float_as_uint(Bs[buf][ks + lk + 4][n0]);
            }
            #pragma unroll
            for (int mi = 0; mi < 2; mi++)
                #pragma unroll
                for (int ni = 0; ni < 8; ni++)
                    mma_tf32(c[mi][ni], af[mi][0], af[mi][1], af[mi][2], af[mi][3],
                             bf[ni][0], bf[ni][1]);
        }

        if (havenext) {
            int nb = buf ^ 1;
            As[nb][akq0 + 0][ar0] = to_tf32(pa0.x);
            As[nb][akq0 + 1][ar0] = to_tf32(pa0.y);
            As[nb][akq0 + 2][ar0] = to_tf32(pa0.z);
            As[nb][akq0 + 3][ar0] = to_tf32(pa0.w);
            As[nb][akq1 + 0][ar1] = to_tf32(pa1.x);
            As[nb][akq1 + 1][ar1] = to_tf32(pa1.y);
            As[nb][akq1 + 2][ar1] = to_tf32(pa1.z);
            As[nb][akq1 + 3][ar1] = to_tf32(pa1.w);
            *(float4*)&Bs[nb][bk0][bc0] = make_float4(to_tf32(pb0.x), to_tf32(pb0.y), to_tf32(pb0.z), to_tf32(pb0.w));
            *(float4*)&Bs[nb][bk1][bc1] = make_float4(to_tf32(pb1.x), to_tf32(pb1.y), to_tf32(pb1.z), to_tf32(pb1.w));
            __syncthreads();
            buf = nb;
        }
    }

    // epilogue
    #pragma unroll
    for (int mi = 0; mi < 2; mi++) {
        #pragma unroll
        for (int ni = 0; ni < 8; ni++) {
            int col = bn + wn + ni * 8 + 2 * lk;
            if (col >= Nc) continue;
            float b0 = bias[col], b1 = bias[col + 1];
            #pragma unroll
            for (int half = 0; half < 2; half++) {
                int row = bm + wm + mi * 16 + lr + half * 8;
                float v0 = c[mi][ni][half * 2 + 0] + b0;
                float v1 = c[mi][ni][half * 2 + 1] + b1;
                if (DOGELU) { v0 = gelu_f(v0); v1 = gelu_f(v1); }
                if (DORES) {
                    const float2 rv = *(const float2*)(res + (size_t)row * Nc + col);
                    v0 += rv.x; v1 += rv.y;
                }
                *(float2*)(Cmat + (size_t)row * Nc + col) = make_float2(v0, v1);
            }
        }
    }
}

// -------------------- deformable sampling core --------------------
__device__ __forceinline__ float dcn_sample(const float* __restrict__ xp, int n, int yi, int xi, int c) {
    if (yi < 1 || yi > HH_ || xi < 1 || xi > WW_) return 0.0f;
    return xp[(size_t)((n * HH_ + (yi - 1)) * WW_ + (xi - 1)) * CC_ + c];
}

__global__ __launch_bounds__(128) void dcn_kernel(const float* __restrict__ xp,
                                                  const float* __restrict__ off,
                                                  const float* __restrict__ ml,
                                                  float* __restrict__ y) {
    int pix = blockIdx.x;
    int c = threadIdx.x;
    int g = c >> 4;
    int n = pix >> 14;
    int hw = pix & 16383;
    int h = hw >> 7;
    int w = hw & 127;
    const float* o = off + (size_t)pix * (GG_ * KP * 2) + g * (KP * 2);
    const float* m = ml + (size_t)pix * (GG_ * KP) + g * KP;
    float lg[KP];
    float mx = -1e30f;
    #pragma unroll
    for (int k = 0; k < KP; k++) { lg[k] = m[k]; mx = fmaxf(mx, lg[k]); }
    float ssum = 0.0f;
    #pragma unroll
    for (int k = 0; k < KP; k++) { lg[k] = expf(lg[k] - mx); ssum += lg[k]; }
    float inv = 1.0f / ssum;
    float acc = 0.0f;
    #pragma unroll
    for (int k = 0; k < KP; k++) {
        float px = (float)(w + (k / 3)) + o[2 * k];
        float py = (float)(h + (k % 3)) + o[2 * k + 1];
        float fx = floorf(px), fy = floorf(py);
        float tx = px - fx, ty = py - fy;
        int x0 = (int)fx, y0 = (int)fy;
        float v00 = dcn_sample(xp, n, y0,     x0,     c);
        float v01 = dcn_sample(xp, n, y0,     x0 + 1, c);
        float v10 = dcn_sample(xp, n, y0 + 1, x0,     c);
        float v11 = dcn_sample(xp, n, y0 + 1, x0 + 1, c);
        float bi = (1.0f - ty) * ((1.0f - tx) * v00 + tx * v01)
                 + ty * ((1.0f - tx) * v10 + tx * v11);
        acc += lg[k] * inv * bi;
    }
    y[(size_t)pix * CC_ + c] = acc;
}

// -------------------- launch --------------------
extern "C" void kernel_launch(void* const* d_in, const int* in_sizes, int n_in,
                              void* d_out, int out_size) {
    const float* x      = (const float*)d_in[0];
    const float* ln1_g  = (const float*)d_in[1];
    const float* ln1_b  = (const float*)d_in[2];
    const float* in_w   = (const float*)d_in[3];
    const float* in_b   = (const float*)d_in[4];
    const float* dw_k   = (const float*)d_in[5];
    const float* dw_b   = (const float*)d_in[6];
    const float* dwln_g = (const float*)d_in[7];
    const float* dwln_b = (const float*)d_in[8];
    const float* off_w  = (const float*)d_in[9];
    const float* off_b  = (const float*)d_in[10];
    const float* mask_w = (const float*)d_in[11];
    const float* mask_b = (const float*)d_in[12];
    const float* out_w  = (const float*)d_in[13];
    const float* out_b  = (const float*)d_in[14];
    const float* ln2_g  = (const float*)d_in[15];
    const float* ln2_b  = (const float*)d_in[16];
    const float* fc1_w  = (const float*)d_in[17];
    const float* fc1_b  = (const float*)d_in[18];
    const float* fc2_w  = (const float*)d_in[19];
    const float* fc2_b  = (const float*)d_in[20];
    float* out = (float*)d_out;

    float *x1n, *xp, *x1, *off, *ml, *y, *x2, *h, *hh;
    cudaGetSymbolAddress((void**)&x1n, g_x1n);
    cudaGetSymbolAddress((void**)&xp,  g_xp);
    cudaGetSymbolAddress((void**)&x1,  g_x1);
    cudaGetSymbolAddress((void**)&off, g_off);
    cudaGetSymbolAddress((void**)&ml,  g_ml);
    cudaGetSymbolAddress((void**)&y,   g_y);
    cudaGetSymbolAddress((void**)&x2,  g_x2);
    cudaGetSymbolAddress((void**)&h,   g_h);
    cudaGetSymbolAddress((void**)&hh,  g_hh);

    const int M = NPIX;          // 65536 rows, M/128 = 512 blocks in y
    dim3 blk256(256);

    // 1. LN1
    ln_kernel<<<NPIX / 8, blk256>>>(x, ln1_g, ln1_b, x1n);
    // 2. input_proj: xp = x1n @ in_w + in_b
    tgemm_kernel<false, false><<<dim3(1, M / 128), blk256>>>(x1n, in_w, in_b, nullptr, xp, M, 128, 128);
    // 3. depthwise conv + LN + GELU -> x1
    dw_ln_gelu_kernel<<<NPIX / 8, blk256>>>(x1n, dw_k, dw_b, dwln_g, dwln_b, x1);
    // 4. offset = x1 @ off_w + off_b   (N=144)
    tgemm_kernel<false, false><<<dim3(2, M / 128), blk256>>>(x1, off_w, off_b, nullptr, off, M, 128, 144);
    // 5. mask logits = x1 @ mask_w + mask_b   (N=72)
    tgemm_kernel<false, false><<<dim3(1, M / 128), blk256>>>(x1, mask_w, mask_b, nullptr, ml, M, 128, 72);
    // 6. deformable sampling (softmax fused)
    dcn_kernel<<<NPIX, dim3(128)>>>(xp, off, ml, y);
    // 7. x2 = y @ out_w + out_b + x
    tgemm_kernel<false, true><<<dim3(1, M / 128), blk256>>>(y, out_w, out_b, x, x2, M, 128, 128);
    // 8. LN2
    ln_kernel<<<NPIX / 8, blk256>>>(x2, ln2_g, ln2_b, h);
    // 9. hh = gelu(h @ fc1_w + fc1_b)   (N=512)
    tgemm_kernel<true, false><<<dim3(4, M / 128), blk256>>>(h, fc1_w, fc1_b, nullptr, hh, M, 128, 512);
    // 10. out = hh @ fc2_w + fc2_b + x2
    tgemm_kernel<false, true><<<dim3(1, M / 128), blk256>>>(hh, fc2_w, fc2_b, x2, out, M, 512, 128);
}

// round 3
// speedup vs baseline: 3.6627x; 1.6003x over previous
#include <cuda_runtime.h>
#include <math.h>
#include <stdint.h>

#define NB   4
#define HH_  128
#define WW_  128
#define CC_  128
#define GG_  8
#define GC_  16
#define KP   9
#define NPIX (NB * HH_ * WW_)   // 65536
#define EPSL 1e-5f

// -------------------- scratch (device globals; no allocation) --------------------
__device__ float g_x1n[(size_t)NPIX * CC_];
__device__ float g_xp [(size_t)NPIX * CC_];
__device__ float g_x1 [(size_t)NPIX * CC_];
__device__ float g_off[(size_t)NPIX * GG_ * KP * 2];
__device__ float g_ml [(size_t)NPIX * GG_ * KP];
__device__ float g_y  [(size_t)NPIX * CC_];
__device__ float g_x2 [(size_t)NPIX * CC_];
__device__ float g_h  [(size_t)NPIX * CC_];
__device__ float g_hh [(size_t)NPIX * 4 * CC_];

__device__ __forceinline__ float gelu_f(float x) {
    return 0.5f * x * (1.0f + erff(x * 0.7071067811865476f));
}

__device__ __forceinline__ void mma_tf32(float c[4],
                                         uint32_t a0, uint32_t a1, uint32_t a2, uint32_t a3,
                                         uint32_t b0, uint32_t b1) {
    asm volatile("mma.sync.aligned.m16n8k8.row.col.f32.tf32.tf32.f32 "
                 "{%0,%1,%2,%3}, {%4,%5,%6,%7}, {%8,%9}, {%0,%1,%2,%3};\n"
                 : "+f"(c[0]), "+f"(c[1]), "+f"(c[2]), "+f"(c[3])
                 : "r"(a0), "r"(a1), "r"(a2), "r"(a3), "r"(b0), "r"(b1));
}

__device__ __forceinline__ void cp16(void* dst, const void* src, bool pred) {
    unsigned sa = (unsigned)__cvta_generic_to_shared(dst);
    int sz = pred ? 16 : 0;
    asm volatile("cp.async.cg.shared.global [%0], [%1], 16, %2;" :: "r"(sa), "l"(src), "r"(sz));
}
__device__ __forceinline__ void cp_commit() { asm volatile("cp.async.commit_group;"); }
__device__ __forceinline__ void cp_wait0()  { asm volatile("cp.async.wait_group 0;"); }

// -------------------- LayerNorm: one warp per pixel --------------------
__global__ __launch_bounds__(256) void ln_kernel(const float* __restrict__ x,
                                                 const float* __restrict__ gw,
                                                 const float* __restrict__ bw,
                                                 float* __restrict__ out) {
    int pix  = blockIdx.x * 8 + (threadIdx.x >> 5);
    int lane = threadIdx.x & 31;
    const float4 v = ((const float4*)(x + (size_t)pix * CC_))[lane];
    float s = v.x + v.y + v.z + v.w;
    #pragma unroll
    for (int o = 16; o > 0; o >>= 1) s += __shfl_xor_sync(0xffffffffu, s, o);
    float mean = s * (1.0f / CC_);
    float dx = v.x - mean, dy = v.y - mean, dz = v.z - mean, dw = v.w - mean;
    float q = dx * dx + dy * dy + dz * dz + dw * dw;
    #pragma unroll
    for (int o = 16; o > 0; o >>= 1) q += __shfl_xor_sync(0xffffffffu, q, o);
    float r = rsqrtf(q * (1.0f / CC_) + EPSL);
    const float4 gg = ((const float4*)gw)[lane];
    const float4 bb = ((const float4*)bw)[lane];
    float4 o4;
    o4.x = dx * r * gg.x + bb.x;
    o4.y = dy * r * gg.y + bb.y;
    o4.z = dz * r * gg.z + bb.z;
    o4.w = dw * r * gg.w + bb.w;
    ((float4*)(out + (size_t)pix * CC_))[lane] = o4;
}

// -------------------- depthwise 3x3 conv + LN + GELU --------------------
__global__ __launch_bounds__(256) void dw_ln_gelu_kernel(const float* __restrict__ x,
                                                         const float* __restrict__ kw,
                                                         const float* __restrict__ kb,
                                                         const float* __restrict__ gw,
                                                         const float* __restrict__ bw,
                                                         float* __restrict__ out) {
    int pix  = blockIdx.x * 8 + (threadIdx.x >> 5);
    int lane = threadIdx.x & 31;
    int n = pix >> 14;
    int hw = pix & 16383;
    int h = hw >> 7;
    int w = hw & 127;
    float4 acc = ((const float4*)kb)[lane];
    #pragma unroll
    for (int ky = 0; ky < 3; ky++) {
        int hh = h + ky - 1;
        if ((unsigned)hh >= (unsigned)HH_) continue;
        #pragma unroll
        for (int kx = 0; kx < 3; kx++) {
            int ww = w + kx - 1;
            if ((unsigned)ww >= (unsigned)WW_) continue;
            const float4 xv = ((const float4*)(x + (size_t)((n * HH_ + hh) * WW_ + ww) * CC_))[lane];
            const float4 kv = ((const float4*)(kw + (size_t)(ky * 3 + kx) * CC_))[lane];
            acc.x += xv.x * kv.x;
            acc.y += xv.y * kv.y;
            acc.z += xv.z * kv.z;
            acc.w += xv.w * kv.w;
        }
    }
    float s = acc.x + acc.y + acc.z + acc.w;
    #pragma unroll
    for (int o = 16; o > 0; o >>= 1) s += __shfl_xor_sync(0xffffffffu, s, o);
    float mean = s * (1.0f / CC_);
    float dx = acc.x - mean, dy = acc.y - mean, dz = acc.z - mean, dw = acc.w - mean;
    float q = dx * dx + dy * dy + dz * dz + dw * dw;
    #pragma unroll
    for (int o = 16; o > 0; o >>= 1) q += __shfl_xor_sync(0xffffffffu, q, o);
    float r = rsqrtf(q * (1.0f / CC_) + EPSL);
    const float4 gg = ((const float4*)gw)[lane];
    const float4 bb = ((const float4*)bw)[lane];
    float4 o4;
    o4.x = gelu_f(dx * r * gg.x + bb.x);
    o4.y = gelu_f(dy * r * gg.y + bb.y);
    o4.z = gelu_f(dz * r * gg.z + bb.z);
    o4.w = gelu_f(dw * r * gg.w + bb.w);
    ((float4*)(out + (size_t)pix * CC_))[lane] = o4;
}

// -------------------- TF32 GEMM: 128x128x16 block, cp.async double-buffer --------------------
// A[M,K] rm, B[K,N] rm, C = A@B + bias (+GELU) (+res). If DOLN: also h = LN(C)*g+b -> Hout
// DOLN requires Nc==128 and gridDim.x==1.
#define LDA 20    // 16 + 4 pad (words per A row)
#define LDB 136   // 128 + 8 pad (words per B k-row)
template <bool DOGELU, bool DORES, bool DOLN>
__global__ __launch_bounds__(256, 2) void tgemm_kernel(const float* __restrict__ A,
                                                       const float* __restrict__ B,
                                                       const float* __restrict__ bias,
                                                       const float* __restrict__ res,
                                                       float* __restrict__ Cmat,
                                                       float* __restrict__ Hout,
                                                       const float* __restrict__ lng,
                                                       const float* __restrict__ lnb,
                                                       int M, int Kd, int Nc) {
    const int BM = 128, BN = 128, BK = 16;
    __shared__ float As[2][BM * LDA];
    __shared__ float Bs[2][BK * LDB];
    __shared__ float s_red[DOLN ? 512 : 4];

    int tid = threadIdx.x;
    int warp = tid >> 5;
    int lane = tid & 31;
    int lr = lane >> 2;       // 0..7
    int lk = lane & 3;        // 0..3
    int bm = blockIdx.y * BM;
    int bn = blockIdx.x * BN;
    int wm = (warp & 3) * 32;
    int wn = (warp >> 2) * 64;

    float c[2][8][4];
    #pragma unroll
    for (int mi = 0; mi < 2; mi++)
        #pragma unroll
        for (int ni = 0; ni < 8; ni++)
            #pragma unroll
            for (int q = 0; q < 4; q++) c[mi][ni][q] = 0.0f;

    auto load_tile = [&](int k0, int b) {
        #pragma unroll
        for (int u = 0; u < 2; u++) {
            int i = tid + u * 256;
            int row = i >> 2, kc = (i & 3) << 2;
            cp16(&As[b][row * LDA + kc], A + (size_t)(bm + row) * Kd + k0 + kc, true);
        }
        #pragma unroll
        for (int u = 0; u < 2; u++) {
            int j = tid + u * 256;
            int row = j >> 5, cc = (j & 31) << 2;
            bool ok = (bn + cc) < Nc;
            const float* sp = ok ? (B + (size_t)(k0 + row) * Nc + bn + cc) : B;
            cp16(&Bs[b][row * LDB + cc], sp, ok);
        }
        cp_commit();
    };

    load_tile(0, 0);

    int nkb = Kd / BK;
    int buf = 0;
    for (int kb = 0; kb < nkb; kb++) {
        cp_wait0();
        __syncthreads();
        if (kb + 1 < nkb) load_tile((kb + 1) * BK, buf ^ 1);

        const float* asb = As[buf];
        const float* bsb = Bs[buf];
        #pragma unroll
        for (int ks = 0; ks < BK; ks += 8) {
            uint32_t af[2][4];
            #pragma unroll
            for (int mi = 0; mi < 2; mi++) {
                const float* ap = asb + (wm + mi * 16 + lr) * LDA + ks + lk;
                af[mi][0] = __float_as_uint(ap[0]);
                af[mi][2] = __float_as_uint(ap[4]);
                af[mi][1] = __float_as_uint(ap[8 * LDA]);
                af[mi][3] = __float_as_uint(ap[8 * LDA + 4]);
            }
            uint32_t bf[8][2];
            #pragma unroll
            for (int ni = 0; ni < 8; ni++) {
                const float* bp = bsb + (ks + lk) * LDB + wn + ni * 8 + lr;
                bf[ni][0] = __float_as_uint(bp[0]);
                bf[ni][1] = __float_as_uint(bp[4 * LDB]);
            }
            #pragma unroll
            for (int mi = 0; mi < 2; mi++)
                #pragma unroll
                for (int ni = 0; ni < 8; ni++)
                    mma_tf32(c[mi][ni], af[mi][0], af[mi][1], af[mi][2], af[mi][3],
                             bf[ni][0], bf[ni][1]);
        }
        buf ^= 1;
    }

    // ---- epilogue: bias (+gelu) (+res); keep final values in c[][] ----
    #pragma unroll
    for (int mi = 0; mi < 2; mi++) {
        #pragma unroll
        for (int ni = 0; ni < 8; ni++) {
            int col = bn + wn + ni * 8 + 2 * lk;
            if (col >= Nc) continue;
            float b0 = bias[col], b1 = bias[col + 1];
            #pragma unroll
            for (int half = 0; half < 2; half++) {
                int row = bm + wm + mi * 16 + half * 8 + lr;
                float v0 = c[mi][ni][half * 2 + 0] + b0;
                float v1 = c[mi][ni][half * 2 + 1] + b1;
                if (DOGELU) { v0 = gelu_f(v0); v1 = gelu_f(v1); }
                if (DORES) {
                    const float2 rv = *(const float2*)(res + (size_t)row * Nc + col);
                    v0 += rv.x; v1 += rv.y;
                }
                c[mi][ni][half * 2 + 0] = v0;
                c[mi][ni][half * 2 + 1] = v1;
                *(float2*)(Cmat + (size_t)row * Nc + col) = make_float2(v0, v1);
            }
        }
    }

    // ---- optional fused LayerNorm over the 128 columns (block owns full rows) ----
    if (DOLN) {
        int wnIdx = warp >> 2;   // 0 or 1
        #pragma unroll
        for (int mi = 0; mi < 2; mi++) {
            #pragma unroll
            for (int half = 0; half < 2; half++) {
                float rs = 0.0f, rq = 0.0f;
                #pragma unroll
                for (int ni = 0; ni < 8; ni++) {
                    float v0 = c[mi][ni][half * 2 + 0];
                    float v1 = c[mi][ni][half * 2 + 1];
                    rs += v0 + v1;
                    rq += v0 * v0 + v1 * v1;
                }
                rs += __shfl_xor_sync(0xffffffffu, rs, 1);
                rq += __shfl_xor_sync(0xffffffffu, rq, 1);
                rs += __shfl_xor_sync(0xffffffffu, rs, 2);
                rq += __shfl_xor_sync(0xffffffffu, rq, 2);
                int r = wm + mi * 16 + half * 8 + lr;
                if (lk == 0) {
                    s_red[r * 2 + wnIdx] = rs;
                    s_red[256 + r * 2 + wnIdx] = rq;
                }
            }
        }
        __syncthreads();
        #pragma unroll
        for (int mi = 0; mi < 2; mi++) {
            #pragma unroll
            for (int half = 0; half < 2; half++) {
                int r = wm + mi * 16 + half * 8 + lr;
                float tot = s_red[r * 2] + s_red[r * 2 + 1];
                float tq  = s_red[256 + r * 2] + s_red[256 + r * 2 + 1];
                float mean = tot * (1.0f / 128.0f);
                float var = tq * (1.0f / 128.0f) - mean * mean;
                float rstd = rsqrtf(var + EPSL);
                int row = bm + r;
                #pragma unroll
                for (int ni = 0; ni < 8; ni++) {
                    int col = wn + ni * 8 + 2 * lk;
                    float g0 = lng[col], g1 = lng[col + 1];
                    float be0 = lnb[col], be1 = lnb[col + 1];
                    float h0 = (c[mi][ni][half * 2 + 0] - mean) * rstd * g0 + be0;
                    float h1 = (c[mi][ni][half * 2 + 1] - mean) * rstd * g1 + be1;
                    *(float2*)(Hout + (size_t)row * 128 + col) = make_float2(h0, h1);
                }
            }
        }
    }
}

// -------------------- deformable sampling: 4 channels / thread, float4 gathers --------------------
__global__ __launch_bounds__(256) void dcn_kernel(const float* __restrict__ xp,
                                                  const float* __restrict__ off,
                                                  const float* __restrict__ ml,
                                                  float* __restrict__ y) {
    int t = threadIdx.x;
    int pix = blockIdx.x * 8 + (t >> 5);
    int lane = t & 31;
    int c4 = lane << 2;
    int g = lane >> 2;
    int n = pix >> 14;
    int hw = pix & 16383;
    int h = hw >> 7;
    int w = hw & 127;
    const float* o = off + (size_t)pix * (GG_ * KP * 2) + g * (KP * 2);
    const float* m = ml + (size_t)pix * (GG_ * KP) + g * KP;
    float lg[KP];
    float mx = -1e30f;
    #pragma unroll
    for (int k = 0; k < KP; k++) { lg[k] = m[k]; mx = fmaxf(mx, lg[k]); }
    float ssum = 0.0f;
    #pragma unroll
    for (int k = 0; k < KP; k++) { lg[k] = expf(lg[k] - mx); ssum += lg[k]; }
    float inv = 1.0f / ssum;

    float4 acc = make_float4(0.f, 0.f, 0.f, 0.f);
    const float* base = xp + (size_t)n * (HH_ * WW_ * CC_) + c4;
    #pragma unroll
    for (int k = 0; k < KP; k++) {
        float px = (float)(w + (k / 3)) + o[2 * k];
        float py = (float)(h + (k % 3)) + o[2 * k + 1];
        float fx = floorf(px), fy = floorf(py);
        float tx = px - fx, ty = py - fy;
        int x0 = (int)fx, y0 = (int)fy;
        float sm = lg[k] * inv;
        float w00 = sm * (1.0f - ty) * (1.0f - tx);
        float w01 = sm * (1.0f - ty) * tx;
        float w10 = sm * ty * (1.0f - tx);
        float w11 = sm * ty * tx;
        #pragma unroll
        for (int corner = 0; corner < 4; corner++) {
            int yy = y0 + (corner >> 1);
            int xx = x0 + (corner & 1);
            float wgt = (corner == 0) ? w00 : (corner == 1) ? w01 : (corner == 2) ? w10 : w11;
            if (yy >= 1 && yy <= HH_ && xx >= 1 && xx <= WW_) {
                const float4 v = *(const float4*)(base + (size_t)((yy - 1) * WW_ + (xx - 1)) * CC_);
                acc.x += wgt * v.x;
                acc.y += wgt * v.y;
                acc.z += wgt * v.z;
                acc.w += wgt * v.w;
            }
        }
    }
    *(float4*)(y + (size_t)pix * CC_ + c4) = acc;
}

// -------------------- launch --------------------
extern "C" void kernel_launch(void* const* d_in, const int* in_sizes, int n_in,
                              void* d_out, int out_size) {
    const float* x      = (const float*)d_in[0];
    const float* ln1_g  = (const float*)d_in[1];
    const float* ln1_b  = (const float*)d_in[2];
    const float* in_w   = (const float*)d_in[3];
    const float* in_b   = (const float*)d_in[4];
    const float* dw_k   = (const float*)d_in[5];
    const float* dw_b   = (const float*)d_in[6];
    const float* dwln_g = (const float*)d_in[7];
    const float* dwln_b = (const float*)d_in[8];
    const float* off_w  = (const float*)d_in[9];
    const float* off_b  = (const float*)d_in[10];
    const float* mask_w = (const float*)d_in[11];
    const float* mask_b = (const float*)d_in[12];
    const float* out_w  = (const float*)d_in[13];
    const float* out_b  = (const float*)d_in[14];
    const float* ln2_g  = (const float*)d_in[15];
    const float* ln2_b  = (const float*)d_in[16];
    const float* fc1_w  = (const float*)d_in[17];
    const float* fc1_b  = (const float*)d_in[18];
    const float* fc2_w  = (const float*)d_in[19];
    const float* fc2_b  = (const float*)d_in[20];
    float* out = (float*)d_out;

    float *x1n, *xp, *x1, *off, *ml, *y, *x2, *h, *hh;
    cudaGetSymbolAddress((void**)&x1n, g_x1n);
    cudaGetSymbolAddress((void**)&xp,  g_xp);
    cudaGetSymbolAddress((void**)&x1,  g_x1);
    cudaGetSymbolAddress((void**)&off, g_off);
    cudaGetSymbolAddress((void**)&ml,  g_ml);
    cudaGetSymbolAddress((void**)&y,   g_y);
    cudaGetSymbolAddress((void**)&x2,  g_x2);
    cudaGetSymbolAddress((void**)&h,   g_h);
    cudaGetSymbolAddress((void**)&hh,  g_hh);

    const int M = NPIX;
    dim3 blk256(256);

    // 1. LN1
    ln_kernel<<<NPIX / 8, blk256>>>(x, ln1_g, ln1_b, x1n);
    // 2. input_proj: xp = x1n @ in_w + in_b
    tgemm_kernel<false, false, false><<<dim3(1, M / 128), blk256>>>(x1n, in_w, in_b, nullptr, xp, nullptr, nullptr, nullptr, M, 128, 128);
    // 3. depthwise conv + LN + GELU -> x1
    dw_ln_gelu_kernel<<<NPIX / 8, blk256>>>(x1n, dw_k, dw_b, dwln_g, dwln_b, x1);
    // 4. offset = x1 @ off_w + off_b   (N=144)
    tgemm_kernel<false, false, false><<<dim3(2, M / 128), blk256>>>(x1, off_w, off_b, nullptr, off, nullptr, nullptr, nullptr, M, 128, 144);
    // 5. mask logits = x1 @ mask_w + mask_b   (N=72)
    tgemm_kernel<false, false, false><<<dim3(1, M / 128), blk256>>>(x1, mask_w, mask_b, nullptr, ml, nullptr, nullptr, nullptr, M, 128, 72);
    // 6. deformable sampling (softmax fused)
    dcn_kernel<<<NPIX / 8, blk256>>>(xp, off, ml, y);
    // 7. x2 = y @ out_w + out_b + x ; h = LN2(x2)   (fused)
    tgemm_kernel<false, true, true><<<dim3(1, M / 128), blk256>>>(y, out_w, out_b, x, x2, h, ln2_g, ln2_b, M, 128, 128);
    // 8. hh = gelu(h @ fc1_w + fc1_b)   (N=512)
    tgemm_kernel<true, false, false><<<dim3(4, M / 128), blk256>>>(h, fc1_w, fc1_b, nullptr, hh, nullptr, nullptr, nullptr, M, 128, 512);
    // 9. out = hh @ fc2_w + fc2_b + x2
    tgemm_kernel<false, true, false><<<dim3(1, M / 128), blk256>>>(hh, fc2_w, fc2_b, x2, out, nullptr, nullptr, nullptr, M, 512, 128);
}

// round 7
// speedup vs baseline: 3.7845x; 1.0332x over previous
#include <cuda_runtime.h>
#include <math.h>
#include <stdint.h>

#define NB   4
#define HH_  128
#define WW_  128
#define CC_  128
#define GG_  8
#define GC_  16
#define KP   9
#define NPIX (NB * HH_ * WW_)   // 65536
#define EPSL 1e-5f
#define NOM  216                 // merged offset(144) + mask(72) cols

// -------------------- scratch (device globals; no allocation) --------------------
__device__ float g_x1n[(size_t)NPIX * CC_];
__device__ float g_xp [(size_t)NPIX * CC_];
__device__ float g_x1 [(size_t)NPIX * CC_];
__device__ float g_omm[(size_t)NPIX * NOM];
__device__ float g_y  [(size_t)NPIX * CC_];
__device__ float g_x2 [(size_t)NPIX * CC_];
__device__ float g_h  [(size_t)NPIX * CC_];
__device__ float g_hh [(size_t)NPIX * 4 * CC_];
__device__ float g_cw [CC_ * NOM];
__device__ float g_cb [NOM];

__device__ __forceinline__ float gelu_f(float x) {
    return 0.5f * x * (1.0f + erff(x * 0.7071067811865476f));
}

__device__ __forceinline__ void mma_tf32(float c[4],
                                         uint32_t a0, uint32_t a1, uint32_t a2, uint32_t a3,
                                         uint32_t b0, uint32_t b1) {
    asm volatile("mma.sync.aligned.m16n8k8.row.col.f32.tf32.tf32.f32 "
                 "{%0,%1,%2,%3}, {%4,%5,%6,%7}, {%8,%9}, {%0,%1,%2,%3};\n"
                 : "+f"(c[0]), "+f"(c[1]), "+f"(c[2]), "+f"(c[3])
                 : "r"(a0), "r"(a1), "r"(a2), "r"(a3), "r"(b0), "r"(b1));
}

__device__ __forceinline__ void cp16(void* dst, const void* src, bool pred) {
    unsigned sa = (unsigned)__cvta_generic_to_shared(dst);
    int sz = pred ? 16 : 0;
    asm volatile("cp.async.cg.shared.global [%0], [%1], 16, %2;" :: "r"(sa), "l"(src), "r"(sz));
}
__device__ __forceinline__ void cp_commit() { asm volatile("cp.async.commit_group;"); }
template<int N> __device__ __forceinline__ void cp_wait() { asm volatile("cp.async.wait_group %0;" :: "n"(N)); }

// -------------------- weight concat: cw = [off_w | mask_w], cb = [off_b | mask_b] --------------------
__global__ __launch_bounds__(256) void concat_wb_kernel(const float* __restrict__ ow,
                                                        const float* __restrict__ mw,
                                                        const float* __restrict__ ob,
                                                        const float* __restrict__ mb,
                                                        float* __restrict__ cw,
                                                        float* __restrict__ cb) {
    int i = blockIdx.x * 256 + threadIdx.x;
    if (i < CC_ * NOM) {
        int r = i / NOM, c = i % NOM;
        cw[i] = (c < 144) ? ow[r * 144 + c] : mw[r * 72 + (c - 144)];
    }
    if (i < NOM) cb[i] = (i < 144) ? ob[i] : mb[i - 144];
}

// -------------------- LayerNorm: one warp per pixel --------------------
__global__ __launch_bounds__(256) void ln_kernel(const float* __restrict__ x,
                                                 const float* __restrict__ gw,
                                                 const float* __restrict__ bw,
                                                 float* __restrict__ out) {
    int pix  = blockIdx.x * 8 + (threadIdx.x >> 5);
    int lane = threadIdx.x & 31;
    const float4 v = ((const float4*)(x + (size_t)pix * CC_))[lane];
    float s = v.x + v.y + v.z + v.w;
    #pragma unroll
    for (int o = 16; o > 0; o >>= 1) s += __shfl_xor_sync(0xffffffffu, s, o);
    float mean = s * (1.0f / CC_);
    float dx = v.x - mean, dy = v.y - mean, dz = v.z - mean, dw = v.w - mean;
    float q = dx * dx + dy * dy + dz * dz + dw * dw;
    #pragma unroll
    for (int o = 16; o > 0; o >>= 1) q += __shfl_xor_sync(0xffffffffu, q, o);
    float r = rsqrtf(q * (1.0f / CC_) + EPSL);
    const float4 gg = ((const float4*)gw)[lane];
    const float4 bb = ((const float4*)bw)[lane];
    float4 o4;
    o4.x = dx * r * gg.x + bb.x;
    o4.y = dy * r * gg.y + bb.y;
    o4.z = dz * r * gg.z + bb.z;
    o4.w = dw * r * gg.w + bb.w;
    ((float4*)(out + (size_t)pix * CC_))[lane] = o4;
}

// -------------------- depthwise 3x3 conv + LN + GELU --------------------
__global__ __launch_bounds__(256) void dw_ln_gelu_kernel(const float* __restrict__ x,
                                                         const float* __restrict__ kw,
                                                         const float* __restrict__ kb,
                                                         const float* __restrict__ gw,
                                                         const float* __restrict__ bw,
                                                         float* __restrict__ out) {
    int pix  = blockIdx.x * 8 + (threadIdx.x >> 5);
    int lane = threadIdx.x & 31;
    int n = pix >> 14;
    int hw = pix & 16383;
    int h = hw >> 7;
    int w = hw & 127;
    float4 acc = ((const float4*)kb)[lane];
    #pragma unroll
    for (int ky = 0; ky < 3; ky++) {
        int hh = h + ky - 1;
        if ((unsigned)hh >= (unsigned)HH_) continue;
        #pragma unroll
        for (int kx = 0; kx < 3; kx++) {
            int ww = w + kx - 1;
            if ((unsigned)ww >= (unsigned)WW_) continue;
            const float4 xv = ((const float4*)(x + (size_t)((n * HH_ + hh) * WW_ + ww) * CC_))[lane];
            const float4 kv = ((const float4*)(kw + (size_t)(ky * 3 + kx) * CC_))[lane];
            acc.x += xv.x * kv.x;
            acc.y += xv.y * kv.y;
            acc.z += xv.z * kv.z;
            acc.w += xv.w * kv.w;
        }
    }
    float s = acc.x + acc.y + acc.z + acc.w;
    #pragma unroll
    for (int o = 16; o > 0; o >>= 1) s += __shfl_xor_sync(0xffffffffu, s, o);
    float mean = s * (1.0f / CC_);
    float dx = acc.x - mean, dy = acc.y - mean, dz = acc.z - mean, dw = acc.w - mean;
    float q = dx * dx + dy * dy + dz * dz + dw * dw;
    #pragma unroll
    for (int o = 16; o > 0; o >>= 1) q += __shfl_xor_sync(0xffffffffu, q, o);
    float r = rsqrtf(q * (1.0f / CC_) + EPSL);
    const float4 gg = ((const float4*)gw)[lane];
    const float4 bb = ((const float4*)bw)[lane];
    float4 o4;
    o4.x = gelu_f(dx * r * gg.x + bb.x);
    o4.y = gelu_f(dy * r * gg.y + bb.y);
    o4.z = gelu_f(dz * r * gg.z + bb.z);
    o4.w = gelu_f(dw * r * gg.w + bb.w);
    ((float4*)(out + (size_t)pix * CC_))[lane] = o4;
}

// -------------------- TF32 GEMM: 128x128xK, 3-stage cp.async pipeline --------------------
#define LDA 20     // A row: 16 + 4 pad words
#define LDB 136    // B k-row: 128 + 8 pad words
#define BMg 128
#define BNg 128
#define BKg 16
#define STAGES 3
#define ASTAGE (BMg * LDA)                 // 2560 words
#define BSTAGE (BKg * LDB)                 // 2176 words
#define SMEM_WORDS (STAGES * (ASTAGE + BSTAGE) + 512)
#define SMEM_BYTES (SMEM_WORDS * 4)

template <bool DOGELU, bool DORES, bool DOLN>
__global__ __launch_bounds__(256, 2) void tgemm_kernel(const float* __restrict__ A,
                                                       const float* __restrict__ B,
                                                       const float* __restrict__ bias,
                                                       const float* __restrict__ res,
                                                       float* __restrict__ Cmat,
                                                       float* __restrict__ Hout,
                                                       const float* __restrict__ lng,
                                                       const float* __restrict__ lnb,
                                                       int M, int Kd, int Nc) {
    extern __shared__ float sm[];
    float* Asm = sm;                         // STAGES * ASTAGE
    float* Bsm = sm + STAGES * ASTAGE;       // STAGES * BSTAGE
    float* s_red = sm + STAGES * (ASTAGE + BSTAGE);

    int tid = threadIdx.x;
    int warp = tid >> 5;
    int lane = tid & 31;
    int lr = lane >> 2;
    int lk = lane & 3;
    int bm = blockIdx.y * BMg;
    int bn = blockIdx.x * BNg;
    int wm = (warp & 3) * 32;
    int wn = (warp >> 2) * 64;

    float c[2][8][4];
    #pragma unroll
    for (int mi = 0; mi < 2; mi++)
        #pragma unroll
        for (int ni = 0; ni < 8; ni++)
            #pragma unroll
            for (int q = 0; q < 4; q++) c[mi][ni][q] = 0.0f;

    auto load_tile = [&](int k0, int st) {
        float* as = Asm + st * ASTAGE;
        float* bs = Bsm + st * BSTAGE;
        #pragma unroll
        for (int u = 0; u < 2; u++) {
            int i = tid + u * 256;
            int row = i >> 2, kc = (i & 3) << 2;
            cp16(&as[row * LDA + kc], A + (size_t)(bm + row) * Kd + k0 + kc, true);
        }
        #pragma unroll
        for (int u = 0; u < 2; u++) {
            int j = tid + u * 256;
            int row = j >> 5, cc = (j & 31) << 2;
            bool ok = (bn + cc) < Nc;
            const float* sp = ok ? (B + (size_t)(k0 + row) * Nc + bn + cc) : B;
            cp16(&bs[row * LDB + cc], sp, ok);
        }
        cp_commit();
    };

    int nkb = Kd / BKg;
    load_tile(0, 0);
    if (nkb > 1) load_tile(BKg, 1);

    int buf = 0;
    for (int kb = 0; kb < nkb; kb++) {
        if (kb + 1 < nkb) cp_wait<1>(); else cp_wait<0>();
        __syncthreads();
        if (kb + 2 < nkb) load_tile((kb + 2) * BKg, (kb + 2) % STAGES);

        const float* asb = Asm + buf * ASTAGE;
        const float* bsb = Bsm + buf * BSTAGE;
        #pragma unroll
        for (int ks = 0; ks < BKg; ks += 8) {
            uint32_t af[2][4];
            #pragma unroll
            for (int mi = 0; mi < 2; mi++) {
                const float* ap = asb + (wm + mi * 16 + lr) * LDA + ks + lk;
                af[mi][0] = __float_as_uint(ap[0]);
                af[mi][2] = __float_as_uint(ap[4]);
                af[mi][1] = __float_as_uint(ap[8 * LDA]);
                af[mi][3] = __float_as_uint(ap[8 * LDA + 4]);
            }
            uint32_t bf[8][2];
            #pragma unroll
            for (int ni = 0; ni < 8; ni++) {
                const float* bp = bsb + (ks + lk) * LDB + wn + ni * 8 + lr;
                bf[ni][0] = __float_as_uint(bp[0]);
                bf[ni][1] = __float_as_uint(bp[4 * LDB]);
            }
            #pragma unroll
            for (int mi = 0; mi < 2; mi++)
                #pragma unroll
                for (int ni = 0; ni < 8; ni++)
                    mma_tf32(c[mi][ni], af[mi][0], af[mi][1], af[mi][2], af[mi][3],
                             bf[ni][0], bf[ni][1]);
        }
        buf = (buf + 1) % STAGES;
    }

    // ---- epilogue ----
    #pragma unroll
    for (int mi = 0; mi < 2; mi++) {
        #pragma unroll
        for (int ni = 0; ni < 8; ni++) {
            int col = bn + wn + ni * 8 + 2 * lk;
            if (col >= Nc) continue;
            float b0 = bias[col], b1 = bias[col + 1];
            #pragma unroll
            for (int half = 0; half < 2; half++) {
                int row = bm + wm + mi * 16 + half * 8 + lr;
                float v0 = c[mi][ni][half * 2 + 0] + b0;
                float v1 = c[mi][ni][half * 2 + 1] + b1;
                if (DOGELU) { v0 = gelu_f(v0); v1 = gelu_f(v1); }
                if (DORES) {
                    const float2 rv = *(const float2*)(res + (size_t)row * Nc + col);
                    v0 += rv.x; v1 += rv.y;
                }
                c[mi][ni][half * 2 + 0] = v0;
                c[mi][ni][half * 2 + 1] = v1;
                *(float2*)(Cmat + (size_t)row * Nc + col) = make_float2(v0, v1);
            }
        }
    }

    if (DOLN) {
        int wnIdx = warp >> 2;
        #pragma unroll
        for (int mi = 0; mi < 2; mi++) {
            #pragma unroll
            for (int half = 0; half < 2; half++) {
                float rs = 0.0f, rq = 0.0f;
                #pragma unroll
                for (int ni = 0; ni < 8; ni++) {
                    float v0 = c[mi][ni][half * 2 + 0];
                    float v1 = c[mi][ni][half * 2 + 1];
                    rs += v0 + v1;
                    rq += v0 * v0 + v1 * v1;
                }
                rs += __shfl_xor_sync(0xffffffffu, rs, 1);
                rq += __shfl_xor_sync(0xffffffffu, rq, 1);
                rs += __shfl_xor_sync(0xffffffffu, rs, 2);
                rq += __shfl_xor_sync(0xffffffffu, rq, 2);
                int r = wm + mi * 16 + half * 8 + lr;
                if (lk == 0) {
                    s_red[r * 2 + wnIdx] = rs;
                    s_red[256 + r * 2 + wnIdx] = rq;
                }
            }
        }
        __syncthreads();
        #pragma unroll
        for (int mi = 0; mi < 2; mi++) {
            #pragma unroll
            for (int half = 0; half < 2; half++) {
                int r = wm + mi * 16 + half * 8 + lr;
                float tot = s_red[r * 2] + s_red[r * 2 + 1];
                float tq  = s_red[256 + r * 2] + s_red[256 + r * 2 + 1];
                float mean = tot * (1.0f / 128.0f);
                float var = tq * (1.0f / 128.0f) - mean * mean;
                float rstd = rsqrtf(var + EPSL);
                int row = bm + r;
                #pragma unroll
                for (int ni = 0; ni < 8; ni++) {
                    int col = wn + ni * 8 + 2 * lk;
                    float g0 = lng[col], g1 = lng[col + 1];
                    float be0 = lnb[col], be1 = lnb[col + 1];
                    float h0 = (c[mi][ni][half * 2 + 0] - mean) * rstd * g0 + be0;
                    float h1 = (c[mi][ni][half * 2 + 1] - mean) * rstd * g1 + be1;
                    *(float2*)(Hout + (size_t)row * 128 + col) = make_float2(h0, h1);
                }
            }
        }
    }
}

// -------------------- deformable sampling: branchless clamped gathers --------------------
__global__ __launch_bounds__(256) void dcn_kernel(const float* __restrict__ xp,
                                                  const float* __restrict__ omm,
                                                  float* __restrict__ y) {
    int t = threadIdx.x;
    int pix = blockIdx.x * 8 + (t >> 5);
    int lane = t & 31;
    int c4 = lane << 2;
    int g = lane >> 2;
    int n = pix >> 14;
    int hw = pix & 16383;
    int h = hw >> 7;
    int w = hw & 127;
    const float* o = omm + (size_t)pix * NOM + g * (KP * 2);
    const float* m = omm + (size_t)pix * NOM + 144 + g * KP;
    float lg[KP];
    float mx = -1e30f;
    #pragma unroll
    for (int k = 0; k < KP; k++) { lg[k] = m[k]; mx = fmaxf(mx, lg[k]); }
    float ssum = 0.0f;
    #pragma unroll
    for (int k = 0; k < KP; k++) { lg[k] = expf(lg[k] - mx); ssum += lg[k]; }
    float inv = 1.0f / ssum;

    float4 acc = make_float4(0.f, 0.f, 0.f, 0.f);
    const float* base = xp + (size_t)n * (HH_ * WW_ * CC_) + c4;
    #pragma unroll
    for (int k = 0; k < KP; k++) {
        float px = (float)(w + (k / 3)) + o[2 * k];
        float py = (float)(h + (k % 3)) + o[2 * k + 1];
        float fx = floorf(px), fy = floorf(py);
        float tx = px - fx, ty = py - fy;
        int x0 = (int)fx, y0 = (int)fy;
        float sm = lg[k] * inv;
        float wc[4];
        wc[0] = sm * (1.0f - ty) * (1.0f - tx);
        wc[1] = sm * (1.0f - ty) * tx;
        wc[2] = sm * ty * (1.0f - tx);
        wc[3] = sm * ty * tx;
        #pragma unroll
        for (int corner = 0; corner < 4; corner++) {
            int yy = y0 + (corner >> 1);
            int xx = x0 + (corner & 1);
            bool ok = (yy >= 1) & (yy <= HH_) & (xx >= 1) & (xx <= WW_);
            int yc = min(max(yy, 1), HH_) - 1;
            int xc = min(max(xx, 1), WW_) - 1;
            float wgt = ok ? wc[corner] : 0.0f;
            const float4 v = *(const float4*)(base + (size_t)(yc * WW_ + xc) * CC_);
            acc.x += wgt * v.x;
            acc.y += wgt * v.y;
            acc.z += wgt * v.z;
            acc.w += wgt * v.w;
        }
    }
    *(float4*)(y + (size_t)pix * CC_ + c4) = acc;
}

// -------------------- launch --------------------
static void set_smem(const void* f) {
    cudaFuncSetAttribute(f, cudaFuncAttributeMaxDynamicSharedMemorySize, SMEM_BYTES);
}

extern "C" void kernel_launch(void* const* d_in, const int* in_sizes, int n_in,
                              void* d_out, int out_size) {
    const float* x      = (const float*)d_in[0];
    const float* ln1_g  = (const float*)d_in[1];
    const float* ln1_b  = (const float*)d_in[2];
    const float* in_w   = (const float*)d_in[3];
    const float* in_b   = (const float*)d_in[4];
    const float* dw_k   = (const float*)d_in[5];
    const float* dw_b   = (const float*)d_in[6];
    const float* dwln_g = (const float*)d_in[7];
    const float* dwln_b = (const float*)d_in[8];
    const float* off_w  = (const float*)d_in[9];
    const float* off_b  = (const float*)d_in[10];
    const float* mask_w = (const float*)d_in[11];
    const float* mask_b = (const float*)d_in[12];
    const float* out_w  = (const float*)d_in[13];
    const float* out_b  = (const float*)d_in[14];
    const float* ln2_g  = (const float*)d_in[15];
    const float* ln2_b  = (const float*)d_in[16];
    const float* fc1_w  = (const float*)d_in[17];
    const float* fc1_b  = (const float*)d_in[18];
    const float* fc2_w  = (const float*)d_in[19];
    const float* fc2_b  = (const float*)d_in[20];
    float* out = (float*)d_out;

    float *x1n, *xp, *x1, *omm, *y, *x2, *h, *hh, *cw, *cb;
    cudaGetSymbolAddress((void**)&x1n, g_x1n);
    cudaGetSymbolAddress((void**)&xp,  g_xp);
    cudaGetSymbolAddress((void**)&x1,  g_x1);
    cudaGetSymbolAddress((void**)&omm, g_omm);
    cudaGetSymbolAddress((void**)&y,   g_y);
    cudaGetSymbolAddress((void**)&x2,  g_x2);
    cudaGetSymbolAddress((void**)&h,   g_h);
    cudaGetSymbolAddress((void**)&hh,  g_hh);
    cudaGetSymbolAddress((void**)&cw,  g_cw);
    cudaGetSymbolAddress((void**)&cb,  g_cb);

    set_smem((const void*)tgemm_kernel<false, false, false>);
    set_smem((const void*)tgemm_kernel<false, true, true>);
    set_smem((const void*)tgemm_kernel<true, false, false>);
    set_smem((const void*)tgemm_kernel<false, true, false>);

    const int M = NPIX;
    dim3 blk256(256);

    // 0. weight concat for merged offset+mask GEMM
    concat_wb_kernel<<<(CC_ * NOM + 255) / 256, blk256>>>(off_w, mask_w, off_b, mask_b, cw, cb);
    // 1. LN1
    ln_kernel<<<NPIX / 8, blk256>>>(x, ln1_g, ln1_b, x1n);
    // 2. input_proj
    tgemm_kernel<false, false, false><<<dim3(1, M / 128), blk256, SMEM_BYTES>>>(x1n, in_w, in_b, nullptr, xp, nullptr, nullptr, nullptr, M, 128, 128);
    // 3. depthwise conv + LN + GELU
    dw_ln_gelu_kernel<<<NPIX / 8, blk256>>>(x1n, dw_k, dw_b, dwln_g, dwln_b, x1);
    // 4. merged offset|mask GEMM (N=216)
    tgemm_kernel<false, false, false><<<dim3(2, M / 128), blk256, SMEM_BYTES>>>(x1, cw, cb, nullptr, omm, nullptr, nullptr, nullptr, M, 128, NOM);
    // 5. deformable sampling (softmax fused)
    dcn_kernel<<<NPIX / 8, blk256>>>(xp, omm, y);
    // 6. x2 = y @ out_w + out_b + x ; h = LN2(x2)
    tgemm_kernel<false, true, true><<<dim3(1, M / 128), blk256, SMEM_BYTES>>>(y, out_w, out_b, x, x2, h, ln2_g, ln2_b, M, 128, 128);
    // 7. hh = gelu(h @ fc1_w + fc1_b)
    tgemm_kernel<true, false, false><<<dim3(4, M / 128), blk256, SMEM_BYTES>>>(h, fc1_w, fc1_b, nullptr, hh, nullptr, nullptr, nullptr, M, 128, 512);
    // 8. out = hh @ fc2_w + fc2_b + x2
    tgemm_kernel<false, true, false><<<dim3(1, M / 128), blk256, SMEM_BYTES>>>(hh, fc2_w, fc2_b, x2, out, nullptr, nullptr, nullptr, M, 512, 128);
}

// round 16
// speedup vs baseline: 3.8254x; 1.0108x over previous
#include <cuda_runtime.h>
#include <math.h>
#include <stdint.h>

#define NB   4
#define HH_  128
#define WW_  128
#define CC_  128
#define GG_  8
#define GC_  16
#define KP   9
#define NPIX (NB * HH_ * WW_)   // 65536
#define EPSL 1e-5f
#define NOM  216                 // merged offset(144) + mask(72) cols

// -------------------- scratch (device globals; no allocation) --------------------
__device__ float g_x1n[(size_t)NPIX * CC_];
__device__ float g_xp [(size_t)NPIX * CC_];
__device__ float g_x1 [(size_t)NPIX * CC_];
__device__ float g_omm[(size_t)NPIX * NOM];
__device__ float g_y  [(size_t)NPIX * CC_];
__device__ float g_x2 [(size_t)NPIX * CC_];
__device__ float g_h  [(size_t)NPIX * CC_];
__device__ float g_hh [(size_t)NPIX * 4 * CC_];
__device__ float g_cw [CC_ * NOM];
__device__ float g_cb [NOM];

__device__ __forceinline__ float gelu_f(float x) {
    return 0.5f * x * (1.0f + erff(x * 0.7071067811865476f));
}

__device__ __forceinline__ void mma_tf32(float c[4],
                                         uint32_t a0, uint32_t a1, uint32_t a2, uint32_t a3,
                                         uint32_t b0, uint32_t b1) {
    asm volatile("mma.sync.aligned.m16n8k8.row.col.f32.tf32.tf32.f32 "
                 "{%0,%1,%2,%3}, {%4,%5,%6,%7}, {%8,%9}, {%0,%1,%2,%3};\n"
                 : "+f"(c[0]), "+f"(c[1]), "+f"(c[2]), "+f"(c[3])
                 : "r"(a0), "r"(a1), "r"(a2), "r"(a3), "r"(b0), "r"(b1));
}

__device__ __forceinline__ void cp16(void* dst, const void* src, bool pred) {
    unsigned sa = (unsigned)__cvta_generic_to_shared(dst);
    int sz = pred ? 16 : 0;
    asm volatile("cp.async.cg.shared.global [%0], [%1], 16, %2;" :: "r"(sa), "l"(src), "r"(sz));
}
__device__ __forceinline__ void cp_commit() { asm volatile("cp.async.commit_group;"); }
template<int N> __device__ __forceinline__ void cp_wait() { asm volatile("cp.async.wait_group %0;" :: "n"(N)); }

// -------------------- weight concat --------------------
__global__ __launch_bounds__(256) void concat_wb_kernel(const float* __restrict__ ow,
                                                        const float* __restrict__ mw,
                                                        const float* __restrict__ ob,
                                                        const float* __restrict__ mb,
                                                        float* __restrict__ cw,
                                                        float* __restrict__ cb) {
    int i = blockIdx.x * 256 + threadIdx.x;
    if (i < CC_ * NOM) {
        int r = i / NOM, c = i % NOM;
        cw[i] = (c < 144) ? ow[r * 144 + c] : mw[r * 72 + (c - 144)];
    }
    if (i < NOM) cb[i] = (i < 144) ? ob[i] : mb[i - 144];
}

// -------------------- LayerNorm: one warp per pixel --------------------
__global__ __launch_bounds__(256) void ln_kernel(const float* __restrict__ x,
                                                 const float* __restrict__ gw,
                                                 const float* __restrict__ bw,
                                                 float* __restrict__ out) {
    int pix  = blockIdx.x * 8 + (threadIdx.x >> 5);
    int lane = threadIdx.x & 31;
    const float4 v = ((const float4*)(x + (size_t)pix * CC_))[lane];
    float s = v.x + v.y + v.z + v.w;
    #pragma unroll
    for (int o = 16; o > 0; o >>= 1) s += __shfl_xor_sync(0xffffffffu, s, o);
    float mean = s * (1.0f / CC_);
    float dx = v.x - mean, dy = v.y - mean, dz = v.z - mean, dw = v.w - mean;
    float q = dx * dx + dy * dy + dz * dz + dw * dw;
    #pragma unroll
    for (int o = 16; o > 0; o >>= 1) q += __shfl_xor_sync(0xffffffffu, q, o);
    float r = rsqrtf(q * (1.0f / CC_) + EPSL);
    const float4 gg = ((const float4*)gw)[lane];
    const float4 bb = ((const float4*)bw)[lane];
    float4 o4;
    o4.x = dx * r * gg.x + bb.x;
    o4.y = dy * r * gg.y + bb.y;
    o4.z = dz * r * gg.z + bb.z;
    o4.w = dw * r * gg.w + bb.w;
    ((float4*)(out + (size_t)pix * CC_))[lane] = o4;
}

// -------------------- depthwise 3x3 conv + LN + GELU, smem halo tile --------------------
// block = 8 consecutive pixels of one row (w0 is 8-aligned). smem tile 3 rows x 10 cols x 128 C.
__global__ __launch_bounds__(256) void dw_ln_gelu_kernel(const float* __restrict__ x,
                                                         const float* __restrict__ kw,
                                                         const float* __restrict__ kb,
                                                         const float* __restrict__ gw,
                                                         const float* __restrict__ bw,
                                                         float* __restrict__ out) {
    __shared__ float tile[3 * 10 * CC_];
    int tid = threadIdx.x;
    int pix0 = blockIdx.x * 8;
    int n = pix0 >> 14;
    int hw0 = pix0 & 16383;
    int h = hw0 >> 7;
    int w0 = hw0 & 127;

    // cooperative halo load: 30 positions x 32 float4 each
    #pragma unroll
    for (int pass = 0; pass < 4; pass++) {
        int p = pass * 8 + (tid >> 5);
        if (p < 30) {
            int r = p / 10;
            int cidx = p % 10;
            int gy = h + r - 1;
            int gx = w0 + cidx - 1;
            int ln_ = tid & 31;
            float4 v = make_float4(0.f, 0.f, 0.f, 0.f);
            if ((unsigned)gy < (unsigned)HH_ && (unsigned)gx < (unsigned)WW_)
                v = ((const float4*)(x + (size_t)((n * HH_ + gy) * WW_ + gx) * CC_))[ln_];
            ((float4*)(tile + (size_t)p * CC_))[ln_] = v;
        }
    }
    __syncthreads();

    int wi = tid >> 5;          // warp = pixel index within the 8-pixel row segment
    int lane = tid & 31;
    float4 acc = ((const float4*)kb)[lane];
    #pragma unroll
    for (int ky = 0; ky < 3; ky++) {
        #pragma unroll
        for (int kx = 0; kx < 3; kx++) {
            const float4 xv = ((const float4*)(tile + (size_t)(ky * 10 + wi + kx) * CC_))[lane];
            const float4 kv = ((const float4*)(kw + (size_t)(ky * 3 + kx) * CC_))[lane];
            acc.x += xv.x * kv.x;
            acc.y += xv.y * kv.y;
            acc.z += xv.z * kv.z;
            acc.w += xv.w * kv.w;
        }
    }
    float s = acc.x + acc.y + acc.z + acc.w;
    #pragma unroll
    for (int o = 16; o > 0; o >>= 1) s += __shfl_xor_sync(0xffffffffu, s, o);
    float mean = s * (1.0f / CC_);
    float dx = acc.x - mean, dy = acc.y - mean, dz = acc.z - mean, dw = acc.w - mean;
    float q = dx * dx + dy * dy + dz * dz + dw * dw;
    #pragma unroll
    for (int o = 16; o > 0; o >>= 1) q += __shfl_xor_sync(0xffffffffu, q, o);
    float r = rsqrtf(q * (1.0f / CC_) + EPSL);
    const float4 gg = ((const float4*)gw)[lane];
    const float4 bb = ((const float4*)bw)[lane];
    float4 o4;
    o4.x = gelu_f(dx * r * gg.x + bb.x);
    o4.y = gelu_f(dy * r * gg.y + bb.y);
    o4.z = gelu_f(dz * r * gg.z + bb.z);
    o4.w = gelu_f(dw * r * gg.w + bb.w);
    ((float4*)(out + (size_t)(pix0 + wi) * CC_))[lane] = o4;
}

// -------------------- TF32 GEMM: 128x128 tile, BK=32, 3-stage cp.async pipeline --------------------
#define LDA 36     // A row: 32 + 4 pad words
#define LDB 136    // B k-row: 128 + 8 pad words
#define BMg 128
#define BNg 128
#define BKg 32
#define STAGES 3
#define ASTAGE (BMg * LDA)                 // 4608 words
#define BSTAGE (BKg * LDB)                 // 4352 words
#define SMEM_WORDS (STAGES * (ASTAGE + BSTAGE) + 512)
#define SMEM_BYTES (SMEM_WORDS * 4)        // 109568 B -> 2 CTAs/SM

template <bool DOGELU, bool DORES, bool DOLN>
__global__ __launch_bounds__(256, 2) void tgemm_kernel(const float* __restrict__ A,
                                                       const float* __restrict__ B,
                                                       const float* __restrict__ bias,
                                                       const float* __restrict__ res,
                                                       float* __restrict__ Cmat,
                                                       float* __restrict__ Hout,
                                                       const float* __restrict__ lng,
                                                       const float* __restrict__ lnb,
                                                       int M, int Kd, int Nc) {
    extern __shared__ float sm[];
    float* Asm = sm;
    float* Bsm = sm + STAGES * ASTAGE;
    float* s_red = sm + STAGES * (ASTAGE + BSTAGE);

    int tid = threadIdx.x;
    int warp = tid >> 5;
    int lane = tid & 31;
    int lr = lane >> 2;
    int lk = lane & 3;
    int bm = blockIdx.y * BMg;
    int bn = blockIdx.x * BNg;
    int wm = (warp & 3) * 32;
    int wn = (warp >> 2) * 64;

    float c[2][8][4];
    #pragma unroll
    for (int mi = 0; mi < 2; mi++)
        #pragma unroll
        for (int ni = 0; ni < 8; ni++)
            #pragma unroll
            for (int q = 0; q < 4; q++) c[mi][ni][q] = 0.0f;

    auto load_tile = [&](int k0, int st) {
        float* as = Asm + st * ASTAGE;
        float* bs = Bsm + st * BSTAGE;
        #pragma unroll
        for (int u = 0; u < 4; u++) {
            int i = tid + u * 256;
            int row = i >> 3, kc = (i & 7) << 2;
            cp16(&as[row * LDA + kc], A + (size_t)(bm + row) * Kd + k0 + kc, true);
        }
        #pragma unroll
        for (int u = 0; u < 4; u++) {
            int j = tid + u * 256;
            int row = j >> 5, cc = (j & 31) << 2;
            bool ok = (bn + cc) < Nc;
            const float* sp = ok ? (B + (size_t)(k0 + row) * Nc + bn + cc) : B;
            cp16(&bs[row * LDB + cc], sp, ok);
        }
        cp_commit();
    };

    int nkb = Kd / BKg;
    load_tile(0, 0);
    if (nkb > 1) load_tile(BKg, 1);

    int buf = 0;
    for (int kb = 0; kb < nkb; kb++) {
        if (kb + 1 < nkb) cp_wait<1>(); else cp_wait<0>();
        __syncthreads();
        if (kb + 2 < nkb) load_tile((kb + 2) * BKg, (kb + 2) % STAGES);

        const float* asb = Asm + buf * ASTAGE;
        const float* bsb = Bsm + buf * BSTAGE;
        #pragma unroll
        for (int ks = 0; ks < BKg; ks += 8) {
            uint32_t af[2][4];
            #pragma unroll
            for (int mi = 0; mi < 2; mi++) {
                const float* ap = asb + (wm + mi * 16 + lr) * LDA + ks + lk;
                af[mi][0] = __float_as_uint(ap[0]);
                af[mi][2] = __float_as_uint(ap[4]);
                af[mi][1] = __float_as_uint(ap[8 * LDA]);
                af[mi][3] = __float_as_uint(ap[8 * LDA + 4]);
            }
            uint32_t bf[8][2];
            #pragma unroll
            for (int ni = 0; ni < 8; ni++) {
                const float* bp = bsb + (ks + lk) * LDB + wn + ni * 8 + lr;
                bf[ni][0] = __float_as_uint(bp[0]);
                bf[ni][1] = __float_as_uint(bp[4 * LDB]);
            }
            #pragma unroll
            for (int mi = 0; mi < 2; mi++)
                #pragma unroll
                for (int ni = 0; ni < 8; ni++)
                    mma_tf32(c[mi][ni], af[mi][0], af[mi][1], af[mi][2], af[mi][3],
                             bf[ni][0], bf[ni][1]);
        }
        buf = (buf + 1) % STAGES;
    }

    // ---- epilogue ----
    #pragma unroll
    for (int mi = 0; mi < 2; mi++) {
        #pragma unroll
        for (int ni = 0; ni < 8; ni++) {
            int col = bn + wn + ni * 8 + 2 * lk;
            if (col >= Nc) continue;
            float b0 = bias[col], b1 = bias[col + 1];
            #pragma unroll
            for (int half = 0; half < 2; half++) {
                int row = bm + wm + mi * 16 + half * 8 + lr;
                float v0 = c[mi][ni][half * 2 + 0] + b0;
                float v1 = c[mi][ni][half * 2 + 1] + b1;
                if (DOGELU) { v0 = gelu_f(v0); v1 = gelu_f(v1); }
                if (DORES) {
                    const float2 rv = *(const float2*)(res + (size_t)row * Nc + col);
                    v0 += rv.x; v1 += rv.y;
                }
                c[mi][ni][half * 2 + 0] = v0;
                c[mi][ni][half * 2 + 1] = v1;
                *(float2*)(Cmat + (size_t)row * Nc + col) = make_float2(v0, v1);
            }
        }
    }

    if (DOLN) {
        int wnIdx = warp >> 2;
        #pragma unroll
        for (int mi = 0; mi < 2; mi++) {
            #pragma unroll
            for (int half = 0; half < 2; half++) {
                float rs = 0.0f, rq = 0.0f;
                #pragma unroll
                for (int ni = 0; ni < 8; ni++) {
                    float v0 = c[mi][ni][half * 2 + 0];
                    float v1 = c[mi][ni][half * 2 + 1];
                    rs += v0 + v1;
                    rq += v0 * v0 + v1 * v1;
                }
                rs += __shfl_xor_sync(0xffffffffu, rs, 1);
                rq += __shfl_xor_sync(0xffffffffu, rq, 1);
                rs += __shfl_xor_sync(0xffffffffu, rs, 2);
                rq += __shfl_xor_sync(0xffffffffu, rq, 2);
                int r = wm + mi * 16 + half * 8 + lr;
                if (lk == 0) {
                    s_red[r * 2 + wnIdx] = rs;
                    s_red[256 + r * 2 + wnIdx] = rq;
                }
            }
        }
        __syncthreads();
        #pragma unroll
        for (int mi = 0; mi < 2; mi++) {
            #pragma unroll
            for (int half = 0; half < 2; half++) {
                int r = wm + mi * 16 + half * 8 + lr;
                float tot = s_red[r * 2] + s_red[r * 2 + 1];
                float tq  = s_red[256 + r * 2] + s_red[256 + r * 2 + 1];
                float mean = tot * (1.0f / 128.0f);
                float var = tq * (1.0f / 128.0f) - mean * mean;
                float rstd = rsqrtf(var + EPSL);
                int row = bm + r;
                #pragma unroll
                for (int ni = 0; ni < 8; ni++) {
                    int col = wn + ni * 8 + 2 * lk;
                    float g0 = lng[col], g1 = lng[col + 1];
                    float be0 = lnb[col], be1 = lnb[col + 1];
                    float h0 = (c[mi][ni][half * 2 + 0] - mean) * rstd * g0 + be0;
                    float h1 = (c[mi][ni][half * 2 + 1] - mean) * rstd * g1 + be1;
                    *(float2*)(Hout + (size_t)row * 128 + col) = make_float2(h0, h1);
                }
            }
        }
    }
}

// -------------------- deformable sampling: branchless clamped gathers --------------------
__global__ __launch_bounds__(256) void dcn_kernel(const float* __restrict__ xp,
                                                  const float* __restrict__ omm,
                                                  float* __restrict__ y) {
    int t = threadIdx.x;
    int pix = blockIdx.x * 8 + (t >> 5);
    int lane = t & 31;
    int c4 = lane << 2;
    int g = lane >> 2;
    int n = pix >> 14;
    int hw = pix & 16383;
    int h = hw >> 7;
    int w = hw & 127;
    const float* o = omm + (size_t)pix * NOM + g * (KP * 2);
    const float* m = omm + (size_t)pix * NOM + 144 + g * KP;
    float lg[KP];
    float mx = -1e30f;
    #pragma unroll
    for (int k = 0; k < KP; k++) { lg[k] = m[k]; mx = fmaxf(mx, lg[k]); }
    float ssum = 0.0f;
    #pragma unroll
    for (int k = 0; k < KP; k++) { lg[k] = expf(lg[k] - mx); ssum += lg[k]; }
    float inv = 1.0f / ssum;

    float4 acc = make_float4(0.f, 0.f, 0.f, 0.f);
    const float* base = xp + (size_t)n * (HH_ * WW_ * CC_) + c4;
    #pragma unroll
    for (int k = 0; k < KP; k++) {
        float px = (float)(w + (k / 3)) + o[2 * k];
        float py = (float)(h + (k % 3)) + o[2 * k + 1];
        float fx = floorf(px), fy = floorf(py);
        float tx = px - fx, ty = py - fy;
        int x0 = (int)fx, y0 = (int)fy;
        float sm = lg[k] * inv;
        float wc[4];
        wc[0] = sm * (1.0f - ty) * (1.0f - tx);
        wc[1] = sm * (1.0f - ty) * tx;
        wc[2] = sm * ty * (1.0f - tx);
        wc[3] = sm * ty * tx;
        #pragma unroll
        for (int corner = 0; corner < 4; corner++) {
            int yy = y0 + (corner >> 1);
            int xx = x0 + (corner & 1);
            bool ok = (yy >= 1) & (yy <= HH_) & (xx >= 1) & (xx <= WW_);
            int yc = min(max(yy, 1), HH_) - 1;
            int xc = min(max(xx, 1), WW_) - 1;
            float wgt = ok ? wc[corner] : 0.0f;
            const float4 v = *(const float4*)(base + (size_t)(yc * WW_ + xc) * CC_);
            acc.x += wgt * v.x;
            acc.y += wgt * v.y;
            acc.z += wgt * v.z;
            acc.w += wgt * v.w;
        }
    }
    *(float4*)(y + (size_t)pix * CC_ + c4) = acc;
}

// -------------------- launch --------------------
static void set_smem(const void* f) {
    cudaFuncSetAttribute(f, cudaFuncAttributeMaxDynamicSharedMemorySize, SMEM_BYTES);
}

extern "C" void kernel_launch(void* const* d_in, const int* in_sizes, int n_in,
                              void* d_out, int out_size) {
    const float* x      = (const float*)d_in[0];
    const float* ln1_g  = (const float*)d_in[1];
    const float* ln1_b  = (const float*)d_in[2];
    const float* in_w   = (const float*)d_in[3];
    const float* in_b   = (const float*)d_in[4];
    const float* dw_k   = (const float*)d_in[5];
    const float* dw_b   = (const float*)d_in[6];
    const float* dwln_g = (const float*)d_in[7];
    const float* dwln_b = (const float*)d_in[8];
    const float* off_w  = (const float*)d_in[9];
    const float* off_b  = (const float*)d_in[10];
    const float* mask_w = (const float*)d_in[11];
    const float* mask_b = (const float*)d_in[12];
    const float* out_w  = (const float*)d_in[13];
    const float* out_b  = (const float*)d_in[14];
    const float* ln2_g  = (const float*)d_in[15];
    const float* ln2_b  = (const float*)d_in[16];
    const float* fc1_w  = (const float*)d_in[17];
    const float* fc1_b  = (const float*)d_in[18];
    const float* fc2_w  = (const float*)d_in[19];
    const float* fc2_b  = (const float*)d_in[20];
    float* out = (float*)d_out;

    float *x1n, *xp, *x1, *omm, *y, *x2, *h, *hh, *cw, *cb;
    cudaGetSymbolAddress((void**)&x1n, g_x1n);
    cudaGetSymbolAddress((void**)&xp,  g_xp);
    cudaGetSymbolAddress((void**)&x1,  g_x1);
    cudaGetSymbolAddress((void**)&omm, g_omm);
    cudaGetSymbolAddress((void**)&y,   g_y);
    cudaGetSymbolAddress((void**)&x2,  g_x2);
    cudaGetSymbolAddress((void**)&h,   g_h);
    cudaGetSymbolAddress((void**)&hh,  g_hh);
    cudaGetSymbolAddress((void**)&cw,  g_cw);
    cudaGetSymbolAddress((void**)&cb,  g_cb);

    set_smem((const void*)tgemm_kernel<false, false, false>);
    set_smem((const void*)tgemm_kernel<false, true, true>);
    set_smem((const void*)tgemm_kernel<true, false, false>);
    set_smem((const void*)tgemm_kernel<false, true, false>);

    const int M = NPIX;
    dim3 blk256(256);

    // 0. weight concat for merged offset+mask GEMM
    concat_wb_kernel<<<(CC_ * NOM + 255) / 256, blk256>>>(off_w, mask_w, off_b, mask_b, cw, cb);
    // 1. LN1
    ln_kernel<<<NPIX / 8, blk256>>>(x, ln1_g, ln1_b, x1n);
    // 2. input_proj
    tgemm_kernel<false, false, false><<<dim3(1, M / 128), blk256, SMEM_BYTES>>>(x1n, in_w, in_b, nullptr, xp, nullptr, nullptr, nullptr, M, 128, 128);
    // 3. depthwise conv + LN + GELU (smem halo tile)
    dw_ln_gelu_kernel<<<NPIX / 8, blk256>>>(x1n, dw_k, dw_b, dwln_g, dwln_b, x1);
    // 4. merged offset|mask GEMM (N=216)
    tgemm_kernel<false, false, false><<<dim3(2, M / 128), blk256, SMEM_BYTES>>>(x1, cw, cb, nullptr, omm, nullptr, nullptr, nullptr, M, 128, NOM);
    // 5. deformable sampling (softmax fused)
    dcn_kernel<<<NPIX / 8, blk256>>>(xp, omm, y);
    // 6. x2 = y @ out_w + out_b + x ; h = LN2(x2)
    tgemm_kernel<false, true, true><<<dim3(1, M / 128), blk256, SMEM_BYTES>>>(y, out_w, out_b, x, x2, h, ln2_g, ln2_b, M, 128, 128);
    // 7. hh = gelu(h @ fc1_w + fc1_b)
    tgemm_kernel<true, false, false><<<dim3(4, M / 128), blk256, SMEM_BYTES>>>(h, fc1_w, fc1_b, nullptr, hh, nullptr, nullptr, nullptr, M, 128, 512);
    // 8. out = hh @ fc2_w + fc2_b + x2
    tgemm_kernel<false, true, false><<<dim3(1, M / 128), blk256, SMEM_BYTES>>>(hh, fc2_w, fc2_b, x2, out, nullptr, nullptr, nullptr, M, 512, 128);
}